// round 1
// baseline (speedup 1.0000x reference)
#include <cuda_runtime.h>
#include <cstdint>

#define BB 8
#define HH 256
#define WW 256
#define HW 65536

// ---------------- scratch (device globals; no allocation) ----------------
__device__ __align__(128) float g_feat[(size_t)BB * 64 * HW];   // lrelu(conv1)
__device__ __align__(128) float g_dx  [(size_t)BB * 64 * HW];   // conv_c0 raw
__device__ __align__(128) float g_actv[(size_t)BB * HW * 128];  // NHWC!
__device__ __align__(128) float g_gb  [(size_t)BB * 128 * HW];  // gamma(0-63), beta(64-127)
__device__ __align__(128) float g_table[BB * 9 * 35 * 128];
__device__ __align__(128) float g_codes[BB * 35 * 64];
__device__ __align__(128) float g_sums [BB * 64 * 36];
__device__ __align__(128) float g_cnt  [BB * 36];
__device__ __align__(128) float g_stats[2 * BB * 64];           // mean, rstd
__device__ __align__(128) float g_w1[2 * 64 * 64 * 9];          // [half][ic][oc][k]
__device__ __align__(128) float g_w2[2 * 128 * 64 * 9];

// ---------------- zero scratch accumulators ----------------
__global__ void k_zero() {
    int i = blockIdx.x * 256 + threadIdx.x;
    if (i < BB * 64 * 36) g_sums[i] = 0.f;
    if (i < BB * 36)      g_cnt[i]  = 0.f;
}

// ---------------- repack weights to [half][ic][oc][k] ----------------
__global__ void k_repack(const float* __restrict__ wc, const float* __restrict__ wc0,
                         const float* __restrict__ wg, const float* __restrict__ wb) {
    int i = blockIdx.x * 256 + threadIdx.x;
    if (i < 73728) {  // g_w1: 2*64*64*9
        int h = i / 36864; int r = i % 36864;
        int ic = r / 576; int r2 = r % 576; int oc = r2 / 9; int k = r2 % 9;
        const float* src = h ? wc0 : wc;
        g_w1[i] = src[(oc * 64 + ic) * 9 + k];
    }
    if (i < 147456) { // g_w2: 2*128*64*9
        int h = i / 73728; int r = i % 73728;
        int ic = r / 576; int r2 = r % 576; int oc = r2 / 9; int k = r2 % 9;
        const float* src = h ? wb : wg;
        g_w2[i] = src[(oc * 128 + ic) * 9 + k];
    }
}

// ---------------- direct 3x3 conv, dual-output (per gridDim.z half) ----------------
// block: 256 thr; tile 32x8 px; thread: 8 px (2x4) x 8 oc. OC per half = 64.
template <int IC, bool NHWC>
__global__ void __launch_bounds__(256, 2)
k_conv(const float* __restrict__ in, const float* __restrict__ wpack,
       const float* __restrict__ bias0, const float* __restrict__ bias1,
       float* __restrict__ out0, float* __restrict__ out1,
       int act0, int act1, int ocb, int choff0, int choff1) {
    constexpr int ICC = 16;
    extern __shared__ float smem[];
    float* s_in = smem;               // [ICC][10][36]
    float* s_w  = smem + ICC * 360;   // [ICC][64][9]

    int b = blockIdx.z >> 1, half = blockIdx.z & 1;
    const float* bias = half ? bias1 : bias0;
    float* out = half ? out1 : out0;
    int act   = half ? act1 : act0;
    int choff = half ? choff1 : choff0;
    int x0 = blockIdx.x * 32, y0 = blockIdx.y * 8;
    int pxg = threadIdx.x & 31, ocg = threadIdx.x >> 5;
    int tx = (pxg & 7) * 4, ty = (pxg >> 3) * 2;

    float acc[8][2][4];
#pragma unroll
    for (int j = 0; j < 8; j++) {
        float bv = bias[ocg * 8 + j];
#pragma unroll
        for (int py = 0; py < 2; py++)
#pragma unroll
            for (int px = 0; px < 4; px++) acc[j][py][px] = bv;
    }

    const float* wbase = wpack + (size_t)half * IC * 576;

    for (int icc = 0; icc < IC; icc += ICC) {
        __syncthreads();
        const float* wsrc = wbase + icc * 576;
        for (int i = threadIdx.x; i < ICC * 576; i += 256) s_w[i] = wsrc[i];
        for (int i = threadIdx.x; i < ICC * 360; i += 256) {
            int ic, r, c;
            if (NHWC) { ic = i & 15; int j2 = i >> 4; r = j2 / 36; c = j2 % 36; }
            else      { ic = i / 360; int j2 = i % 360; r = j2 / 36; c = j2 % 36; }
            int gy = y0 - 1 + r, gx = x0 - 1 + c;
            float v = 0.f;
            if (c < 34 && (unsigned)gy < 256u && (unsigned)gx < 256u) {
                if (NHWC) v = in[((size_t)b * HW + gy * 256 + gx) * IC + icc + ic];
                else      v = in[((size_t)(b * IC + icc + ic)) * HW + gy * 256 + gx];
            }
            s_in[ic * 360 + r * 36 + c] = v;
        }
        __syncthreads();
#pragma unroll 2
        for (int ic = 0; ic < ICC; ic++) {
            float rin[4][6];
#pragma unroll
            for (int r = 0; r < 4; r++)
#pragma unroll
                for (int c = 0; c < 6; c++)
                    rin[r][c] = s_in[ic * 360 + (ty + r) * 36 + tx + c];
#pragma unroll
            for (int j = 0; j < 8; j++) {
                const float* wp = &s_w[ic * 576 + (ocg * 8 + j) * 9];
                float w0 = wp[0], w1 = wp[1], w2 = wp[2];
                float w3 = wp[3], w4 = wp[4], w5 = wp[5];
                float w6 = wp[6], w7 = wp[7], w8 = wp[8];
#pragma unroll
                for (int py = 0; py < 2; py++)
#pragma unroll
                    for (int px = 0; px < 4; px++) {
                        float v = acc[j][py][px];
                        v = fmaf(w0, rin[py + 0][px + 0], v);
                        v = fmaf(w1, rin[py + 0][px + 1], v);
                        v = fmaf(w2, rin[py + 0][px + 2], v);
                        v = fmaf(w3, rin[py + 1][px + 0], v);
                        v = fmaf(w4, rin[py + 1][px + 1], v);
                        v = fmaf(w5, rin[py + 1][px + 2], v);
                        v = fmaf(w6, rin[py + 2][px + 0], v);
                        v = fmaf(w7, rin[py + 2][px + 1], v);
                        v = fmaf(w8, rin[py + 2][px + 2], v);
                        acc[j][py][px] = v;
                    }
            }
        }
    }
#pragma unroll
    for (int j = 0; j < 8; j++) {
        int oc = ocg * 8 + j + choff;
#pragma unroll
        for (int py = 0; py < 2; py++) {
            int y = y0 + ty + py;
            float4 v;
            v.x = acc[j][py][0]; v.y = acc[j][py][1];
            v.z = acc[j][py][2]; v.w = acc[j][py][3];
            if (act == 1) {
                v.x = v.x >= 0.f ? v.x : 0.2f * v.x;
                v.y = v.y >= 0.f ? v.y : 0.2f * v.y;
                v.z = v.z >= 0.f ? v.z : 0.2f * v.z;
                v.w = v.w >= 0.f ? v.w : 0.2f * v.w;
            }
            *(float4*)&out[((size_t)(b * ocb + oc)) * HW + y * 256 + x0 + tx] = v;
        }
    }
}

// ---------------- instance-norm stats over g_dx ----------------
__global__ void k_stats() {
    int bc = blockIdx.x;  // 512 = B*64
    int tid = threadIdx.x;
    const float4* p = (const float4*)(g_dx + (size_t)bc * HW);
    float s = 0.f, s2 = 0.f;
    for (int i = tid; i < HW / 4; i += 256) {
        float4 v = p[i];
        s  += v.x + v.y + v.z + v.w;
        s2 += v.x * v.x + v.y * v.y + v.z * v.z + v.w * v.w;
    }
    __shared__ float rs[256], rq[256];
    rs[tid] = s; rq[tid] = s2;
    __syncthreads();
    for (int o = 128; o > 0; o >>= 1) {
        if (tid < o) { rs[tid] += rs[tid + o]; rq[tid] += rq[tid + o]; }
        __syncthreads();
    }
    if (tid == 0) {
        float m = rs[0] * (1.f / HW);
        float var = rq[0] * (1.f / HW) - m * m;
        g_stats[bc] = m;
        g_stats[512 + bc] = rsqrtf(var + 1e-5f);
    }
}

// ---------------- masked per-class mean pooling ----------------
__global__ void k_pool(const int* __restrict__ seg, const float* __restrict__ bg,
                       const float* __restrict__ mask) {
    __shared__ float s_sum[64 * 36];
    __shared__ float s_cnt[36];
    int tid = threadIdx.x;
    for (int i = tid; i < 64 * 36; i += 256) s_sum[i] = 0.f;
    if (tid < 36) s_cnt[tid] = 0.f;
    __syncthreads();
    int b = blockIdx.y;
    int lane = tid & 31, cg = tid >> 5;
    int base = blockIdx.x * 4096;
    for (int p0 = 0; p0 < 4096; p0 += 32) {
        int p = base + p0 + lane;
        int s = seg[b * HW + p];
        bool q = (bg[b * HW + p] * (1.f - mask[b * HW + p])) > 0.f;
        if (q && cg == 0) atomicAdd(&s_cnt[s], 1.f);
        if (q) {
#pragma unroll
            for (int cc = 0; cc < 8; cc++) {
                int c = cg + cc * 8;
                float f = g_feat[((size_t)(b * 64 + c)) * HW + p];
                atomicAdd(&s_sum[c * 36 + s], f);
            }
        }
    }
    __syncthreads();
    for (int i = tid; i < 64 * 36; i += 256) {
        float v = s_sum[i];
        if (v != 0.f) atomicAdd(&g_sums[b * 2304 + i], v);
    }
    if (tid < 36 && s_cnt[tid] != 0.f) atomicAdd(&g_cnt[b * 36 + tid], s_cnt[tid]);
}

// ---------------- codes (mean + keep mask) ----------------
__global__ void k_codes() {
    int i = blockIdx.x * 256 + threadIdx.x;
    if (i >= BB * 35 * 64) return;
    int b = i / (35 * 64); int s = (i / 64) % 35; int f = i & 63;
    float cnt = g_cnt[b * 36 + s];
    bool keep = !(s >= 24 && s <= 33);
    float v = 0.f;
    if (cnt > 0.f && keep) v = g_sums[b * 2304 + f * 36 + s] / cnt;
    g_codes[i] = v;  // [b][s][f]
}

// ---------------- fold codes + one-hot channels through w_sh -> table ----------------
__global__ void k_table(const float* __restrict__ w_sh) {
    int blk = blockIdx.x;  // b*315 + k*35 + s
    int b = blk / 315; int rem = blk % 315; int k = rem / 35; int s = rem % 35;
    __shared__ float sc[64];
    int o = threadIdx.x;  // 128
    if (o < 64) sc[o] = g_codes[(b * 35 + s) * 64 + o];
    __syncthreads();
    float acc = w_sh[(o * 99 + 64 + s) * 9 + k];
#pragma unroll 8
    for (int f = 0; f < 64; f++)
        acc = fmaf(w_sh[(o * 99 + f) * 9 + k], sc[f], acc);
    g_table[((b * 9 + k) * 35 + s) * 128 + o] = acc;
}

// ---------------- actv = relu(b_sh + 3x3 table-gather conv), NHWC output ----------------
__global__ void k_actv(const int* __restrict__ seg, const float* __restrict__ bg,
                       const float* __restrict__ bsh) {
    __shared__ int ns[324];
    int b = blockIdx.z;
    int x0 = blockIdx.x * 16, y0 = blockIdx.y * 16;
    int tid = threadIdx.x;
    for (int i = tid; i < 324; i += 256) {
        int r = i / 18, c = i % 18;
        int gy = y0 - 1 + r, gx = x0 - 1 + c;
        int v = -1;
        if ((unsigned)gy < 256u && (unsigned)gx < 256u) {
            int p = gy * 256 + gx;
            if (bg[b * HW + p] > 0.f) v = seg[b * HW + p];
        }
        ns[i] = v;
    }
    __syncthreads();
    int oq = tid & 31, pg = tid >> 5;
    const float4* T4 = (const float4*)g_table + (size_t)b * 9 * 35 * 32;
    float4 bias = ((const float4*)bsh)[oq];
    for (int pp = pg * 32; pp < pg * 32 + 32; pp++) {
        int ly = pp >> 4, lx = pp & 15;
        float4 a = bias;
#pragma unroll
        for (int ky = 0; ky < 3; ky++)
#pragma unroll
            for (int kx = 0; kx < 3; kx++) {
                int idx = ns[(ly + ky) * 18 + lx + kx];
                if (idx >= 0) {
                    float4 t = T4[((ky * 3 + kx) * 35 + idx) * 32 + oq];
                    a.x += t.x; a.y += t.y; a.z += t.z; a.w += t.w;
                }
            }
        a.x = fmaxf(a.x, 0.f); a.y = fmaxf(a.y, 0.f);
        a.z = fmaxf(a.z, 0.f); a.w = fmaxf(a.w, 0.f);
        int gp = (y0 + ly) * 256 + x0 + lx;
        ((float4*)g_actv)[((size_t)b * HW + gp) * 32 + oq] = a;
    }
}

// ---------------- final: lrelu(instnorm(dx)*(1+gamma)+beta) ----------------
__global__ void k_final(float* __restrict__ out) {
    size_t gi = (size_t)blockIdx.x * 256 + threadIdx.x;  // float4 index
    size_t e = gi * 4;
    int b = (int)(e / ((size_t)64 * HW));
    int c = (int)((e / HW) & 63);
    size_t p = e % HW;
    float4 dx = ((const float4*)g_dx)[gi];
    float4 ga = ((const float4*)g_gb)[((size_t)(b * 128 + c) * HW + p) / 4];
    float4 be = ((const float4*)g_gb)[((size_t)(b * 128 + 64 + c) * HW + p) / 4];
    float m = g_stats[b * 64 + c], r = g_stats[512 + b * 64 + c];
    float4 o;
    {
        float v;
        v = (dx.x - m) * r * (1.f + ga.x) + be.x; o.x = v >= 0.f ? v : 0.2f * v;
        v = (dx.y - m) * r * (1.f + ga.y) + be.y; o.y = v >= 0.f ? v : 0.2f * v;
        v = (dx.z - m) * r * (1.f + ga.z) + be.z; o.z = v >= 0.f ? v : 0.2f * v;
        v = (dx.w - m) * r * (1.f + ga.w) + be.w; o.w = v >= 0.f ? v : 0.2f * v;
    }
    ((float4*)out)[gi] = o;
}

// ---------------- host ----------------
extern "C" void kernel_launch(void* const* d_in, const int* in_sizes, int n_in,
                              void* d_out, int out_size) {
    const float* featmap_in = (const float*)d_in[0];
    const int*   seg        = (const int*)  d_in[1];
    const float* bg         = (const float*)d_in[2];
    const float* mask       = (const float*)d_in[3];
    const float* w_conv     = (const float*)d_in[4];
    const float* b_conv     = (const float*)d_in[5];
    const float* w_c0       = (const float*)d_in[6];
    const float* b_c0       = (const float*)d_in[7];
    const float* w_sh       = (const float*)d_in[8];
    const float* b_sh       = (const float*)d_in[9];
    const float* w_g        = (const float*)d_in[10];
    const float* b_g        = (const float*)d_in[11];
    const float* w_b        = (const float*)d_in[12];
    const float* b_b        = (const float*)d_in[13];

    const int SMEM_BYTES = (16 * 360 + 16 * 576) * 4;  // 59904
    cudaFuncSetAttribute(k_conv<64, false>, cudaFuncAttributeMaxDynamicSharedMemorySize, SMEM_BYTES);
    cudaFuncSetAttribute(k_conv<128, true>, cudaFuncAttributeMaxDynamicSharedMemorySize, SMEM_BYTES);

    void *p_feat, *p_dx, *p_actv, *p_gb, *p_w1, *p_w2;
    cudaGetSymbolAddress(&p_feat, g_feat);
    cudaGetSymbolAddress(&p_dx,   g_dx);
    cudaGetSymbolAddress(&p_actv, g_actv);
    cudaGetSymbolAddress(&p_gb,   g_gb);
    cudaGetSymbolAddress(&p_w1,   g_w1);
    cudaGetSymbolAddress(&p_w2,   g_w2);

    k_zero<<<72, 256>>>();
    k_repack<<<576, 256>>>(w_conv, w_c0, w_g, w_b);

    // conv1 (lrelu -> g_feat) + conv_c0 (raw -> g_dx), fused over gridDim.z halves
    dim3 cgrid(8, 32, 16);
    k_conv<64, false><<<cgrid, 256, SMEM_BYTES>>>(
        featmap_in, (const float*)p_w1, b_conv, b_c0,
        (float*)p_feat, (float*)p_dx, 1, 0, 64, 0, 0);

    k_stats<<<512, 256>>>();
    k_pool<<<dim3(16, 8), 256>>>(seg, bg, mask);
    k_codes<<<70, 256>>>();
    k_table<<<2520, 128>>>(w_sh);
    k_actv<<<dim3(16, 16, 8), 256>>>(seg, bg, b_sh);

    // gamma (half0) + beta (half1) -> g_gb channels [0:64) / [64:128)
    k_conv<128, true><<<cgrid, 256, SMEM_BYTES>>>(
        (const float*)p_actv, (const float*)p_w2, b_g, b_b,
        (float*)p_gb, (float*)p_gb, 0, 0, 128, 0, 64);

    k_final<<<32768, 256>>>((float*)d_out);
}